// round 1
// baseline (speedup 1.0000x reference)
#include <cuda_runtime.h>
#include <math.h>

// Problem constants (match reference)
#define BB 16
#define HH 288
#define WW 800
#define NPIX (HH * WW)          // 230400
#define NVEC (NPIX / 4)         // 57600 float4 groups per plane per batch
#define NL 4                    // tracked labels 1..4 (label 0 stats are dead)
#define DELTA_V 0.5f

// Scratch (device globals; no allocation allowed)
__device__ float g_sums[BB][NL][4];   // embedding sums per (b, label, dim)
__device__ float g_cnts[BB][NL];      // pixel counts per (b, label)
__device__ float g_hinge[BB][NL];     // hinge sums per (b, label)
__device__ float g_means[BB][NL][4];  // centroids
__device__ float g_ce[2];             // {sum(w*nll), sum(w)}

__device__ __forceinline__ float warp_sum(float v) {
    #pragma unroll
    for (int o = 16; o > 0; o >>= 1) v += __shfl_xor_sync(0xffffffffu, v, o);
    return v;
}

// ---------------------------------------------------------------------------
__global__ void zero_scratch() {
    int t = threadIdx.x;
    float* s = &g_sums[0][0][0];
    for (int i = t; i < BB * NL * 4; i += blockDim.x) s[i] = 0.f;
    float* c = &g_cnts[0][0];
    for (int i = t; i < BB * NL; i += blockDim.x) c[i] = 0.f;
    float* h = &g_hinge[0][0];
    for (int i = t; i < BB * NL; i += blockDim.x) h[i] = 0.f;
    if (t < 2) g_ce[t] = 0.f;
}

// ---------------------------------------------------------------------------
// Pass 1: per-(b,label) embedding sums + counts, and weighted CE partials.
// grid = (CHUNKS, BB), block = 256. Vectorized float4 loads.
__global__ void __launch_bounds__(256, 8)
pass1_kernel(const float* __restrict__ emb,
             const float* __restrict__ seg2,
             const int*   __restrict__ lab) {
    const int b = blockIdx.y;
    const float* e0 = emb  + (size_t)b * 4 * NPIX;
    const float* s0 = seg2 + (size_t)b * 2 * NPIX;
    const int*   l0 = lab  + (size_t)b * NPIX;

    float acc[NL][4];
    float cnt[NL];
    #pragma unroll
    for (int l = 0; l < NL; l++) {
        cnt[l] = 0.f;
        #pragma unroll
        for (int d = 0; d < 4; d++) acc[l][d] = 0.f;
    }
    float wnll = 0.f, wsum = 0.f;

    const int stride = gridDim.x * blockDim.x;
    for (int i = blockIdx.x * blockDim.x + threadIdx.x; i < NVEC; i += stride) {
        float4 e0v = __ldg((const float4*)(e0)           + i);
        float4 e1v = __ldg((const float4*)(e0 + NPIX)    + i);
        float4 e2v = __ldg((const float4*)(e0 + 2*NPIX)  + i);
        float4 e3v = __ldg((const float4*)(e0 + 3*NPIX)  + i);
        int4   lv  = __ldg((const int4*)(l0) + i);
        float4 g0v = __ldg((const float4*)(s0)           + i);
        float4 g1v = __ldg((const float4*)(s0 + NPIX)    + i);

        const float ed0[4] = {e0v.x, e0v.y, e0v.z, e0v.w};
        const float ed1[4] = {e1v.x, e1v.y, e1v.z, e1v.w};
        const float ed2[4] = {e2v.x, e2v.y, e2v.z, e2v.w};
        const float ed3[4] = {e3v.x, e3v.y, e3v.z, e3v.w};
        const int   lbs[4] = {lv.x, lv.y, lv.z, lv.w};
        const float ga[4]  = {g0v.x, g0v.y, g0v.z, g0v.w};
        const float gb[4]  = {g1v.x, g1v.y, g1v.z, g1v.w};

        #pragma unroll
        for (int p = 0; p < 4; p++) {
            const int L = lbs[p];
            // per-label predicated accumulation (compile-time indices only)
            #pragma unroll
            for (int l = 0; l < NL; l++) {
                if (L == l + 1) {
                    acc[l][0] += ed0[p];
                    acc[l][1] += ed1[p];
                    acc[l][2] += ed2[p];
                    acc[l][3] += ed3[p];
                    cnt[l]    += 1.f;
                }
            }
            // weighted binary cross-entropy (log-softmax over 2 logits)
            const float a = ga[p], c = gb[p];
            const float mx = fmaxf(a, c);
            const float mn = fminf(a, c);
            const float lse = mx + log1pf(__expf(mn - mx));
            const int   tgt = (L > 0);
            const float nll = lse - (tgt ? c : a);
            const float w   = tgt ? 1.0f : 0.5f;
            wnll += w * nll;
            wsum += w;
        }
    }

    // Block reduce: warp butterfly -> shared atomics -> global atomics
    __shared__ float sh[NL * 5 + 2];   // 16 sums + 4 cnts + wnll + wsum = 22
    if (threadIdx.x < NL * 5 + 2) sh[threadIdx.x] = 0.f;
    __syncthreads();

    const int lane = threadIdx.x & 31;
    float vals[NL * 5 + 2];
    #pragma unroll
    for (int l = 0; l < NL; l++) {
        #pragma unroll
        for (int d = 0; d < 4; d++) vals[l * 4 + d] = acc[l][d];
        vals[16 + l] = cnt[l];
    }
    vals[20] = wnll;
    vals[21] = wsum;

    #pragma unroll
    for (int j = 0; j < NL * 5 + 2; j++) {
        float r = warp_sum(vals[j]);
        if (lane == 0) atomicAdd(&sh[j], r);
    }
    __syncthreads();

    if (threadIdx.x < NL * 5 + 2) {
        const int j = threadIdx.x;
        const float v = sh[j];
        if (j < 16)       atomicAdd(&g_sums[b][j >> 2][j & 3], v);
        else if (j < 20)  atomicAdd(&g_cnts[b][j - 16], v);
        else if (j == 20) atomicAdd(&g_ce[0], v);
        else              atomicAdd(&g_ce[1], v);
    }
}

// ---------------------------------------------------------------------------
// Pass 1.5: centroids. One tiny block.
__global__ void means_kernel() {
    const int t = threadIdx.x;           // 0..63
    if (t < BB * NL) {
        const int b = t / NL, l = t % NL;
        const float inv = 1.0f / fmaxf(g_cnts[b][l], 1.0f);
        #pragma unroll
        for (int d = 0; d < 4; d++) g_means[b][l][d] = g_sums[b][l][d] * inv;
    }
}

// ---------------------------------------------------------------------------
// Pass 2: per-pixel distance to own centroid -> hinge sums per (b, label).
__global__ void __launch_bounds__(256, 8)
pass2_kernel(const float* __restrict__ emb,
             const int*   __restrict__ lab) {
    const int b = blockIdx.y;
    const float* e0 = emb + (size_t)b * 4 * NPIX;
    const int*   l0 = lab + (size_t)b * NPIX;

    __shared__ float sm[NL][4];
    if (threadIdx.x < NL * 4)
        sm[threadIdx.x >> 2][threadIdx.x & 3] =
            g_means[b][threadIdx.x >> 2][threadIdx.x & 3];
    __syncthreads();

    float hs[NL] = {0.f, 0.f, 0.f, 0.f};

    const int stride = gridDim.x * blockDim.x;
    for (int i = blockIdx.x * blockDim.x + threadIdx.x; i < NVEC; i += stride) {
        float4 e0v = __ldg((const float4*)(e0)          + i);
        float4 e1v = __ldg((const float4*)(e0 + NPIX)   + i);
        float4 e2v = __ldg((const float4*)(e0 + 2*NPIX) + i);
        float4 e3v = __ldg((const float4*)(e0 + 3*NPIX) + i);
        int4   lv  = __ldg((const int4*)(l0) + i);

        const float ed0[4] = {e0v.x, e0v.y, e0v.z, e0v.w};
        const float ed1[4] = {e1v.x, e1v.y, e1v.z, e1v.w};
        const float ed2[4] = {e2v.x, e2v.y, e2v.z, e2v.w};
        const float ed3[4] = {e3v.x, e3v.y, e3v.z, e3v.w};
        const int   lbs[4] = {lv.x, lv.y, lv.z, lv.w};

        #pragma unroll
        for (int p = 0; p < 4; p++) {
            const int L = lbs[p];
            if (L > 0) {
                const int li = L - 1;   // dynamic only into SHARED (fine)
                const float d0 = ed0[p] - sm[li][0];
                const float d1 = ed1[p] - sm[li][1];
                const float d2 = ed2[p] - sm[li][2];
                const float d3 = ed3[p] - sm[li][3];
                const float sq = d0*d0 + d1*d1 + d2*d2 + d3*d3;
                const float dist = sqrtf(sq);         // sqrt(0)=0, matches safe_norm
                const float t = fmaxf(dist - DELTA_V, 0.0f);
                const float hv = t * t;
                #pragma unroll
                for (int l = 0; l < NL; l++)
                    if (li == l) hs[l] += hv;
            }
        }
    }

    __shared__ float sh[NL];
    if (threadIdx.x < NL) sh[threadIdx.x] = 0.f;
    __syncthreads();
    const int lane = threadIdx.x & 31;
    #pragma unroll
    for (int l = 0; l < NL; l++) {
        float r = warp_sum(hs[l]);
        if (lane == 0) atomicAdd(&sh[l], r);
    }
    __syncthreads();
    if (threadIdx.x < NL) atomicAdd(&g_hinge[b][threadIdx.x], sh[threadIdx.x]);
}

// ---------------------------------------------------------------------------
__global__ void finalize_kernel(float* __restrict__ out) {
    const int b = threadIdx.x;  // one warp
    float var_b = 0.f;
    if (b < BB) {
        float nlanes = 0.f, s = 0.f;
        #pragma unroll
        for (int l = 0; l < NL; l++) {
            const float c = g_cnts[b][l];
            const bool pres = (c > 0.f);
            nlanes += pres ? 1.f : 0.f;
            if (pres) s += g_hinge[b][l] / fmaxf(c, 1.f);
        }
        var_b = s / fmaxf(nlanes, 1.f);
    }
    const float tot = warp_sum(var_b);
    if (threadIdx.x == 0) {
        const float var_loss = tot / (float)BB;
        const float seg_loss = g_ce[0] / g_ce[1];
        // dist_loss == 0 identically (delta_d added to all distances),
        // reg_loss == 0. loss = seg + var.
        out[0] = seg_loss + var_loss;
    }
}

// ---------------------------------------------------------------------------
extern "C" void kernel_launch(void* const* d_in, const int* in_sizes, int n_in,
                              void* d_out, int out_size) {
    const float* emb  = (const float*)d_in[0];  // [16,4,288,800] f32
    const float* bseg = (const float*)d_in[1];  // [16,2,288,800] f32
    const int*   lab  = (const int*)  d_in[2];  // [16,288,800]   i32
    float* out = (float*)d_out;

    (void)in_sizes; (void)n_in; (void)out_size;

    zero_scratch<<<1, 256>>>();
    dim3 grid(72, BB);
    pass1_kernel<<<grid, 256>>>(emb, bseg, lab);
    means_kernel<<<1, 64>>>();
    pass2_kernel<<<grid, 256>>>(emb, lab);
    finalize_kernel<<<1, 32>>>(out);
}

// round 2
// speedup vs baseline: 1.4955x; 1.4955x over previous
#include <cuda_runtime.h>
#include <math.h>

// Problem constants
#define BB 16
#define NPIX (288 * 800)        // 230400
#define NVEC (NPIX / 4)         // 57600 float4 groups per plane per batch
#define BPB 75                  // blocks per batch: 75 * 256 * 3 = 57600
#define TPB 256
#define IL 3                    // groups per thread (compile-time trip count)
#define NL 4                    // tracked labels 1..4 (label 0 stats dead)
#define NP1 22                  // pass1 partials: 16 sums + 4 cnts + wnll + wsum
#define DELTA_V 0.5f

// Scratch (device globals; no allocation allowed)
__device__ float g_p1[BB][BPB][NP1];   // pass1 per-block partials
__device__ float g_p2[BB][BPB][NL];    // pass2 per-block hinge partials
__device__ float g_means[BB][NL][4];
__device__ float g_cnts[BB][NL];
__device__ float g_ceb[BB][2];         // per-batch {wnll, wsum}
__device__ int   g_ticket;             // pass2 last-block ticket (reset by reduce)

__device__ __forceinline__ float warp_sum(float v) {
    #pragma unroll
    for (int o = 16; o > 0; o >>= 1) v += __shfl_xor_sync(0xffffffffu, v, o);
    return v;
}

// ---------------------------------------------------------------------------
// Pass 1: per-(b,label) embedding sums + counts + weighted CE partials.
// grid = (BPB, BB), block = 256. Exactly 3 float4-groups per thread,
// fully unrolled so ptxas front-batches the loads (high MLP).
__global__ void __launch_bounds__(TPB, 4)
pass1_kernel(const float* __restrict__ emb,
             const float* __restrict__ seg2,
             const int*   __restrict__ lab) {
    const int b = blockIdx.y;
    const float* e0 = emb  + (size_t)b * 4 * NPIX;
    const float* s0 = seg2 + (size_t)b * 2 * NPIX;
    const int*   l0 = lab  + (size_t)b * NPIX;
    const int base = blockIdx.x * (TPB * IL) + threadIdx.x;

    float acc[NL][4];
    float cnt[NL];
    #pragma unroll
    for (int l = 0; l < NL; l++) {
        cnt[l] = 0.f;
        #pragma unroll
        for (int d = 0; d < 4; d++) acc[l][d] = 0.f;
    }
    float wnll = 0.f, wsum = 0.f;

    #pragma unroll
    for (int k = 0; k < IL; k++) {
        const int i = base + k * TPB;
        float4 e0v = __ldg((const float4*)(e0)            + i);
        float4 e1v = __ldg((const float4*)(e0 + NPIX)     + i);
        float4 e2v = __ldg((const float4*)(e0 + 2*NPIX)   + i);
        float4 e3v = __ldg((const float4*)(e0 + 3*NPIX)   + i);
        int4   lv  = __ldg((const int4*)(l0) + i);
        float4 g0v = __ldg((const float4*)(s0)            + i);
        float4 g1v = __ldg((const float4*)(s0 + NPIX)     + i);

        const float ed0[4] = {e0v.x, e0v.y, e0v.z, e0v.w};
        const float ed1[4] = {e1v.x, e1v.y, e1v.z, e1v.w};
        const float ed2[4] = {e2v.x, e2v.y, e2v.z, e2v.w};
        const float ed3[4] = {e3v.x, e3v.y, e3v.z, e3v.w};
        const int   lbs[4] = {lv.x, lv.y, lv.z, lv.w};
        const float ga[4]  = {g0v.x, g0v.y, g0v.z, g0v.w};
        const float gb[4]  = {g1v.x, g1v.y, g1v.z, g1v.w};

        #pragma unroll
        for (int p = 0; p < 4; p++) {
            const int L = lbs[p];
            #pragma unroll
            for (int l = 0; l < NL; l++) {
                if (L == l + 1) {
                    acc[l][0] += ed0[p];
                    acc[l][1] += ed1[p];
                    acc[l][2] += ed2[p];
                    acc[l][3] += ed3[p];
                    cnt[l]    += 1.f;
                }
            }
            // weighted binary CE (log-softmax over 2 logits), fast math
            const float a = ga[p], c = gb[p];
            const float mx = fmaxf(a, c);
            const float mn = fminf(a, c);
            const float lse = mx + __logf(1.0f + __expf(mn - mx));
            const int   tgt = (L > 0);
            const float nll = lse - (tgt ? c : a);
            const float w   = tgt ? 1.0f : 0.5f;
            wnll += w * nll;
            wsum += w;
        }
    }

    // Block reduce 22 values: warp butterfly -> shared -> per-block store.
    __shared__ float sh[TPB / 32][NP1];
    const int wid = threadIdx.x >> 5, lane = threadIdx.x & 31;

    float vals[NP1];
    #pragma unroll
    for (int l = 0; l < NL; l++) {
        #pragma unroll
        for (int d = 0; d < 4; d++) vals[l * 4 + d] = acc[l][d];
        vals[16 + l] = cnt[l];
    }
    vals[20] = wnll;
    vals[21] = wsum;

    #pragma unroll
    for (int j = 0; j < NP1; j++) {
        float r = warp_sum(vals[j]);
        if (lane == 0) sh[wid][j] = r;
    }
    __syncthreads();
    if (threadIdx.x < NP1) {
        float s = 0.f;
        #pragma unroll
        for (int w = 0; w < TPB / 32; w++) s += sh[w][threadIdx.x];
        g_p1[b][blockIdx.x][threadIdx.x] = s;
    }
}

// ---------------------------------------------------------------------------
// Reduce: sum 75 per-block partials per batch; compute means/counts/CE.
// Also resets the pass2 ticket. grid = BB, block = 128.
__global__ void reduce_means_kernel() {
    const int b = blockIdx.x;
    const int t = threadIdx.x;
    __shared__ float sh[5][NP1];
    __shared__ float tot[NP1];

    if (t < 5 * NP1) {                   // 110 threads: 5 chunks x 22 cols
        const int col = t % NP1;
        const int part = t / NP1;
        float s = 0.f;
        #pragma unroll
        for (int r = 0; r < 15; r++) s += g_p1[b][part * 15 + r][col];
        sh[part][col] = s;
    }
    __syncthreads();
    if (t < NP1) {
        tot[t] = sh[0][t] + sh[1][t] + sh[2][t] + sh[3][t] + sh[4][t];
    }
    __syncthreads();
    if (t < 16) {
        const int l = t >> 2, d = t & 3;
        g_means[b][l][d] = tot[t] / fmaxf(tot[16 + l], 1.0f);
    } else if (t < 20) {
        g_cnts[b][t - 16] = tot[t];
    } else if (t == 20) {
        g_ceb[b][0] = tot[20];
    } else if (t == 21) {
        g_ceb[b][1] = tot[21];
    }
    if (b == 0 && t == 127) g_ticket = 0;
}

// ---------------------------------------------------------------------------
// Pass 2: per-pixel hinge vs own centroid; last block finalizes the loss.
// grid = (BPB, BB), block = 256.
__global__ void __launch_bounds__(TPB, 4)
pass2_kernel(const float* __restrict__ emb,
             const int*   __restrict__ lab,
             float* __restrict__ out) {
    const int b = blockIdx.y;
    const float* e0 = emb + (size_t)b * 4 * NPIX;
    const int*   l0 = lab + (size_t)b * NPIX;
    const int base = blockIdx.x * (TPB * IL) + threadIdx.x;

    __shared__ float sm[NL][4];
    if (threadIdx.x < NL * 4)
        sm[threadIdx.x >> 2][threadIdx.x & 3] =
            g_means[b][threadIdx.x >> 2][threadIdx.x & 3];
    __syncthreads();

    float hs[NL] = {0.f, 0.f, 0.f, 0.f};

    #pragma unroll
    for (int k = 0; k < IL; k++) {
        const int i = base + k * TPB;
        float4 e0v = __ldg((const float4*)(e0)          + i);
        float4 e1v = __ldg((const float4*)(e0 + NPIX)   + i);
        float4 e2v = __ldg((const float4*)(e0 + 2*NPIX) + i);
        float4 e3v = __ldg((const float4*)(e0 + 3*NPIX) + i);
        int4   lv  = __ldg((const int4*)(l0) + i);

        const float ed0[4] = {e0v.x, e0v.y, e0v.z, e0v.w};
        const float ed1[4] = {e1v.x, e1v.y, e1v.z, e1v.w};
        const float ed2[4] = {e2v.x, e2v.y, e2v.z, e2v.w};
        const float ed3[4] = {e3v.x, e3v.y, e3v.z, e3v.w};
        const int   lbs[4] = {lv.x, lv.y, lv.z, lv.w};

        #pragma unroll
        for (int p = 0; p < 4; p++) {
            const int L = lbs[p];
            if (L > 0) {
                const int li = L - 1;    // dynamic index into shared (fine)
                const float d0 = ed0[p] - sm[li][0];
                const float d1 = ed1[p] - sm[li][1];
                const float d2 = ed2[p] - sm[li][2];
                const float d3 = ed3[p] - sm[li][3];
                const float sq = d0*d0 + d1*d1 + d2*d2 + d3*d3;
                const float dist = sqrtf(sq);
                const float tt = fmaxf(dist - DELTA_V, 0.0f);
                const float hv = tt * tt;
                #pragma unroll
                for (int l = 0; l < NL; l++)
                    if (li == l) hs[l] += hv;
            }
        }
    }

    // Block reduce 4 hinge sums -> per-block partial.
    __shared__ float shh[TPB / 32][NL];
    const int wid = threadIdx.x >> 5, lane = threadIdx.x & 31;
    #pragma unroll
    for (int l = 0; l < NL; l++) {
        float r = warp_sum(hs[l]);
        if (lane == 0) shh[wid][l] = r;
    }
    __syncthreads();
    if (threadIdx.x < NL) {
        float s = 0.f;
        #pragma unroll
        for (int w = 0; w < TPB / 32; w++) s += shh[w][threadIdx.x];
        g_p2[b][blockIdx.x][threadIdx.x] = s;
    }

    // Last-block finalize (deterministic: sums all partials regardless of order)
    __shared__ int is_last;
    __threadfence();
    if (threadIdx.x == 0) {
        const int old = atomicAdd(&g_ticket, 1);
        is_last = (old == BB * BPB - 1);
    }
    __syncthreads();
    if (!is_last) return;

    // 64 (b,label) bins x 4 sub-accumulators = 256 threads
    __shared__ float fh[BB * NL][4];
    {
        const int bin = threadIdx.x >> 2;   // 0..63
        const int sub = threadIdx.x & 3;
        const int b2 = bin >> 2, l = bin & 3;
        float s = 0.f;
        for (int r = sub; r < BPB; r += 4) s += g_p2[b2][r][l];
        fh[bin][sub] = s;
    }
    __syncthreads();
    if (threadIdx.x == 0) {
        float var_tot = 0.f, wnll = 0.f, wsum = 0.f;
        #pragma unroll
        for (int bb = 0; bb < BB; bb++) {
            float nlanes = 0.f, sv = 0.f;
            #pragma unroll
            for (int l = 0; l < NL; l++) {
                const float c = g_cnts[bb][l];
                if (c > 0.f) {
                    nlanes += 1.f;
                    const float h = fh[bb * NL + l][0] + fh[bb * NL + l][1]
                                  + fh[bb * NL + l][2] + fh[bb * NL + l][3];
                    sv += h / c;
                }
            }
            var_tot += sv / fmaxf(nlanes, 1.f);
            wnll += g_ceb[bb][0];
            wsum += g_ceb[bb][1];
        }
        // dist_loss == 0 identically; reg_loss == 0.
        out[0] = wnll / wsum + var_tot / (float)BB;
    }
}

// ---------------------------------------------------------------------------
extern "C" void kernel_launch(void* const* d_in, const int* in_sizes, int n_in,
                              void* d_out, int out_size) {
    const float* emb  = (const float*)d_in[0];  // [16,4,288,800] f32
    const float* bseg = (const float*)d_in[1];  // [16,2,288,800] f32
    const int*   lab  = (const int*)  d_in[2];  // [16,288,800]   i32
    float* out = (float*)d_out;
    (void)in_sizes; (void)n_in; (void)out_size;

    dim3 grid(BPB, BB);
    pass1_kernel<<<grid, TPB>>>(emb, bseg, lab);
    reduce_means_kernel<<<BB, 128>>>();
    pass2_kernel<<<grid, TPB>>>(emb, lab, out);
}